// round 11
// baseline (speedup 1.0000x reference)
#include <cuda_runtime.h>
#include <math_constants.h>

#define NM 1024
#define HH 256
#define WW 256
#define HW (HH*WW)
#define PARTS 4
#define MAXC 256      // cap on valid candidates (E[cnt]~123, sigma~10)
#define MAXW 8        // ceil(MAXC/32)
#define PMAX 256      // max bitonic pad

// ---------------- device scratch (no allocations allowed) ----------------
__device__ __align__(16) int   g_hi4 [NM*PARTS];
__device__ __align__(16) int   g_lo4 [NM*PARTS];
__device__ __align__(16) int   g_mnx4[NM*PARTS];
__device__ __align__(16) int   g_mxx4[NM*PARTS];
__device__ __align__(16) int   g_mny4[NM*PARTS];
__device__ __align__(16) int   g_mxy4[NM*PARTS];
__device__ __align__(16) float g_gated[NM];
__device__ int g_ticket[NM];   // zero-init; self-resetting per launch
__device__ int g_total;        // zero-init; NMS block resets after consuming

// ============ mega kernel: stats + last-arriver zeroing + in-kernel NMS ============
__global__ __launch_bounds__(256)
void mega_kernel(const float* __restrict__ logits,
                 const float* __restrict__ iou_preds,
                 float* __restrict__ out,
                 float* __restrict__ out_keep,
                 float* __restrict__ out_boxes) {
    // NMS shared state (only block NM*PARTS uses the big arrays)
    __shared__ int      s_scan[256];
    __shared__ int      s_cnt;
    __shared__ float    s_cs[MAXC];
    __shared__ float4   s_cb[MAXC];
    __shared__ int      s_co[MAXC];
    __shared__ float    s_sc[PMAX];
    __shared__ int      s_si[PMAX];
    __shared__ float4   s_sb[MAXC];
    __shared__ int      s_so[MAXC];
    __shared__ unsigned s_mat[MAXC][MAXW];
    __shared__ unsigned s_keepw[MAXW];
    // stats-role reduce state
    __shared__ int s_hi[8], s_lo[8], s_mnx[8], s_mxx[8], s_mny[8], s_mxy[8];
    __shared__ int s_last;

    const int t = threadIdx.x;

    if (blockIdx.x < NM * PARTS) {
        // ---------------- stats role: one mask-quarter ----------------
        const int b  = blockIdx.x;
        const int n  = b >> 2;
        const int rq = b & 3;
        const float4* __restrict__ p =
            (const float4*)(logits + (size_t)n * HW) + (rq << 12);

        const int xq = t & 63;
        const int y0 = t >> 6;

        int hi = 0, lo = 0;
        unsigned rowm = 0, colm = 0;

        #pragma unroll 8
        for (int k = 0; k < 16; k++) {
            int yy = y0 + (k << 2);
            float4 v = p[(yy << 6) + xq];
            hi += (v.x > 1.f) + (v.y > 1.f) + (v.z > 1.f) + (v.w > 1.f);
            lo += (v.x > -1.f) + (v.y > -1.f) + (v.z > -1.f) + (v.w > -1.f);
            unsigned pm = (unsigned)(v.x > 0.f)        | ((unsigned)(v.y > 0.f) << 1)
                        | ((unsigned)(v.z > 0.f) << 2) | ((unsigned)(v.w > 0.f) << 3);
            colm |= pm;
            rowm |= (pm ? 1u : 0u) << k;
        }

        int mnx = WW, mxx = -1, mny = 64, mxy = -1;
        if (colm) { int bx = xq << 2; mnx = bx + __ffs(colm) - 1; mxx = bx + 31 - __clz(colm); }
        if (rowm) { mny = y0 + ((__ffs(rowm) - 1) << 2); mxy = y0 + ((31 - __clz(rowm)) << 2); }

        #pragma unroll
        for (int o = 16; o > 0; o >>= 1) {
            hi  += __shfl_xor_sync(0xffffffffu, hi, o);
            lo  += __shfl_xor_sync(0xffffffffu, lo, o);
            mnx  = min(mnx, __shfl_xor_sync(0xffffffffu, mnx, o));
            mxx  = max(mxx, __shfl_xor_sync(0xffffffffu, mxx, o));
            mny  = min(mny, __shfl_xor_sync(0xffffffffu, mny, o));
            mxy  = max(mxy, __shfl_xor_sync(0xffffffffu, mxy, o));
        }

        int w = t >> 5;
        if ((t & 31) == 0) {
            s_hi[w] = hi; s_lo[w] = lo;
            s_mnx[w] = mnx; s_mxx[w] = mxx; s_mny[w] = mny; s_mxy[w] = mxy;
        }
        __syncthreads();
        if (t == 0) {
            int thi = 0, tlo = 0, tmnx = WW, tmxx = -1, tmny = 64, tmxy = -1;
            #pragma unroll
            for (int i = 0; i < 8; i++) {
                thi += s_hi[i]; tlo += s_lo[i];
                tmnx = min(tmnx, s_mnx[i]); tmxx = max(tmxx, s_mxx[i]);
                tmny = min(tmny, s_mny[i]); tmxy = max(tmxy, s_mxy[i]);
            }
            g_hi4[b] = thi; g_lo4[b] = tlo;
            g_mnx4[b] = tmnx; g_mxx4[b] = tmxx;
            if (tmxy < 0) { g_mny4[b] = HH; g_mxy4[b] = -1; }
            else          { g_mny4[b] = tmny + (rq << 6); g_mxy4[b] = tmxy + (rq << 6); }

            __threadfence();                       // publish partials
            int old = atomicAdd(&g_ticket[n], 1);
            atomicAdd(&g_total, 1);
            s_last = (old == 3);
            if (old == 3) g_ticket[n] = 0;         // self-reset for next graph replay
        }
        __syncthreads();

        if (s_last) {
            __threadfence();                       // acquire partials of sibling quarters
            int4 H = *(const int4*)&g_hi4[n << 2];
            int4 L = *(const int4*)&g_lo4[n << 2];
            int thi = H.x + H.y + H.z + H.w;
            int tlo = L.x + L.y + L.z + L.w;
            float stab = (float)thi / fmaxf((float)tlo, 1.0f);
            bool valid = (iou_preds[n] > 0.88f) && (stab >= 0.95f);
            if (!valid) {
                // zero the ENTIRE mask now: overlaps other blocks' read stream
                float4* __restrict__ o = (float4*)(out + (size_t)n * HW);
                const float4 z = make_float4(0.f, 0.f, 0.f, 0.f);
                #pragma unroll 8
                for (int k = 0; k < 64; k++)
                    o[t + (k << 8)] = z;
            }
        }
        return;
    }

    // ---------------- NMS role: block NM*PARTS, waits for all partials ----------------
    if (t == 0) {
        while (*(volatile int*)&g_total < NM * PARTS) __nanosleep(64);
    }
    __syncthreads();
    __threadfence();

    const int4* __restrict__ ph  = (const int4*)g_hi4;
    const int4* __restrict__ pl  = (const int4*)g_lo4;
    const int4* __restrict__ px0 = (const int4*)g_mnx4;
    const int4* __restrict__ px1 = (const int4*)g_mxx4;
    const int4* __restrict__ py0 = (const int4*)g_mny4;
    const int4* __restrict__ py1 = (const int4*)g_mxy4;

    bool   vld[4];
    float  scr[4];
    float4 box[4];
    #pragma unroll
    for (int r = 0; r < 4; r++) {
        int m = (t << 2) + r;
        int4 H = ph[m], L = pl[m], X0 = px0[m], X1 = px1[m], Y0 = py0[m], Y1 = py1[m];
        int hi = H.x + H.y + H.z + H.w;
        int lo = L.x + L.y + L.z + L.w;
        int mnx = min(min(X0.x, X0.y), min(X0.z, X0.w));
        int mxx = max(max(X1.x, X1.y), max(X1.z, X1.w));
        int mny = min(min(Y0.x, Y0.y), min(Y0.z, Y0.w));
        int mxy = max(max(Y1.x, Y1.y), max(Y1.z, Y1.w));
        float stab = (float)hi / fmaxf((float)lo, 1.0f);
        float sc = iou_preds[m];
        vld[r] = (sc > 0.88f) && (stab >= 0.95f);
        scr[r] = sc;
        box[r] = (mxy < 0) ? make_float4(0.f, 0.f, 0.f, 0.f)
                           : make_float4((float)mnx, (float)mny, (float)mxx, (float)mxy);
    }

    const float4 z4 = make_float4(0.f, 0.f, 0.f, 0.f);
    ((float4*)g_gated)[t] = z4;
    if (out_keep) ((float4*)out_keep)[t] = z4;
    if (out_boxes) {
        float4* ob = (float4*)out_boxes;
        #pragma unroll
        for (int r = 0; r < 4; r++) ob[(t << 2) + r] = box[r];
    }

    // deterministic order-preserving compaction via scan
    int c = (int)vld[0] + vld[1] + vld[2] + vld[3];
    s_scan[t] = c;
    __syncthreads();
    for (int off = 1; off < 256; off <<= 1) {
        int x = s_scan[t];
        int a = (t >= off) ? s_scan[t - off] : 0;
        __syncthreads();
        s_scan[t] = x + a;
        __syncthreads();
    }
    if (t == 255) s_cnt = s_scan[255];
    int pos = s_scan[t] - c;
    #pragma unroll
    for (int r = 0; r < 4; r++) {
        if (vld[r]) {
            if (pos < MAXC) { s_cs[pos] = scr[r]; s_cb[pos] = box[r]; s_co[pos] = (t << 2) + r; }
            pos++;
        }
    }
    __syncthreads();
    const int cnt = min(s_cnt, MAXC);

    if (cnt > 0) {
        int P = 32;
        while (P < cnt) P <<= 1;                   // <= 256
        for (int i = t; i < P; i += 256) { s_sc[i] = (i < cnt) ? s_cs[i] : -CUDART_INF_F; s_si[i] = i; }
        __syncthreads();
        for (int k = 2; k <= P; k <<= 1) {
            for (int j = k >> 1; j > 0; j >>= 1) {
                for (int i = t; i < P; i += 256) {
                    int ixj = i ^ j;
                    if (ixj > i) {
                        float a = s_sc[i], bb = s_sc[ixj];
                        if (((i & k) == 0) ? (a < bb) : (a > bb)) {
                            s_sc[i] = bb; s_sc[ixj] = a;
                            int ti = s_si[i]; s_si[i] = s_si[ixj]; s_si[ixj] = ti;
                        }
                    }
                }
                __syncthreads();
            }
        }
        for (int i = t; i < cnt; i += 256) {
            int src = s_si[i];
            s_sb[i] = s_cb[src];
            s_so[i] = s_co[src];
        }
        __syncthreads();

        // suppression bit-matrix: row i, bit j (j>i) set iff IoU(i,j) > 0.7
        const int W = (cnt + 31) >> 5;
        for (int u = t; u < cnt * W; u += 256) {
            int i = u / W, w = u - i * W;
            float4 bi = s_sb[i];
            float ai = fmaxf(bi.z - bi.x, 0.f) * fmaxf(bi.w - bi.y, 0.f);
            unsigned bits = 0;
            int jb = w << 5;
            for (int b2 = 0; b2 < 32; b2++) {
                int j = jb + b2;
                if (j < cnt && j > i) {
                    float4 bj = s_sb[j];
                    float x0 = fmaxf(bi.x, bj.x), y0 = fmaxf(bi.y, bj.y);
                    float x1 = fminf(bi.z, bj.z), y1 = fminf(bi.w, bj.w);
                    float inter = fmaxf(x1 - x0, 0.f) * fmaxf(y1 - y0, 0.f);
                    float aj = fmaxf(bj.z - bj.x, 0.f) * fmaxf(bj.w - bj.y, 0.f);
                    if (inter / fmaxf(ai + aj - inter, 1e-6f) > 0.7f) bits |= 1u << b2;
                }
            }
            s_mat[i][w] = bits;
        }
        __syncthreads();

        // greedy chain as bitmask scan (single thread)
        if (t == 0) {
            unsigned kw[MAXW];
            #pragma unroll
            for (int w = 0; w < MAXW; w++) {
                if (w < W - 1)       kw[w] = 0xFFFFFFFFu;
                else if (w == W - 1) kw[w] = (cnt & 31) ? ((1u << (cnt & 31)) - 1u) : 0xFFFFFFFFu;
                else                 kw[w] = 0u;
            }
            for (int i = 0; i < cnt; i++) {
                if ((kw[i >> 5] >> (i & 31)) & 1u) {
                    for (int w = 0; w < W; w++) kw[w] &= ~s_mat[i][w];
                }
            }
            for (int w = 0; w < W; w++) s_keepw[w] = kw[w];
        }
        __syncthreads();

        for (int i = t; i < cnt; i += 256) {
            if ((s_keepw[i >> 5] >> (i & 31)) & 1u) {
                int o = s_so[i];
                g_gated[o] = s_sc[i];
                if (out_keep) out_keep[o] = 1.0f;
            }
        }
    }

    __syncthreads();
    if (t == 0) g_total = 0;                       // reset for next graph replay
}

// ============ gate kernel: valid masks only (invalid already zeroed) ============
__global__ __launch_bounds__(256) void gate_kernel(const float* __restrict__ logits,
                                                   const float* __restrict__ iou_preds,
                                                   float* __restrict__ out) {
    const int b  = blockIdx.x;
    const int n  = b >> 2;
    const int rq = b & 3;

    int4 H = *(const int4*)&g_hi4[n << 2];
    int4 L = *(const int4*)&g_lo4[n << 2];
    int hi = H.x + H.y + H.z + H.w;
    int lo = L.x + L.y + L.z + L.w;
    float stab = (float)hi / fmaxf((float)lo, 1.0f);
    bool valid = (iou_preds[n] > 0.88f) && (stab >= 0.95f);
    if (!valid) return;

    float g = g_gated[n];
    float4* __restrict__ o = (float4*)(out + (size_t)n * HW) + (rq << 12);

    if (g == 0.f) {                                // valid but NMS-suppressed
        const float4 z = make_float4(0.f, 0.f, 0.f, 0.f);
        #pragma unroll
        for (int k = 0; k < 16; k++)
            o[threadIdx.x + (k << 8)] = z;
    } else {
        const float4* __restrict__ p = (const float4*)(logits + (size_t)n * HW) + (rq << 12);
        #pragma unroll 4
        for (int k = 0; k < 16; k++) {
            int q = threadIdx.x + (k << 8);
            float4 v = p[q];
            float4 r;
            r.x = g / (1.f + __expf(-v.x));
            r.y = g / (1.f + __expf(-v.y));
            r.z = g / (1.f + __expf(-v.z));
            r.w = g / (1.f + __expf(-v.w));
            o[q] = r;
        }
    }
}

// ---------------- launch ----------------
extern "C" void kernel_launch(void* const* d_in, const int* in_sizes, int n_in,
                              void* d_out, int out_size) {
    const float* logits;
    const float* iou;
    if (in_sizes[0] == NM) { iou = (const float*)d_in[0]; logits = (const float*)d_in[1]; }
    else                   { logits = (const float*)d_in[0]; iou = (const float*)d_in[1]; }

    float* out = (float*)d_out;
    const size_t nhw = (size_t)NM * HW;
    float* out_keep  = nullptr;
    float* out_boxes = nullptr;
    if ((size_t)out_size >= nhw + NM)          out_keep  = out + nhw;
    if ((size_t)out_size >= nhw + NM + 4 * NM) out_boxes = out + nhw + NM;

    mega_kernel<<<NM * PARTS + 1, 256>>>(logits, iou, out, out_keep, out_boxes);
    gate_kernel<<<NM * PARTS, 256>>>(logits, iou, out);
}

// round 13
// speedup vs baseline: 1.1984x; 1.1984x over previous
#include <cuda_runtime.h>
#include <math_constants.h>

#define NM 1024
#define HH 256
#define WW 256
#define HW (HH*WW)
#define PARTS 4
#define SEGS 16       // output segments per mask in finish kernel
#define MAXC 256      // cap on valid candidates (E[cnt]~123, sigma~10)
#define MAXW 8        // ceil(MAXC/32)
#define PMAX 256      // max bitonic pad

// ---------------- device scratch (no allocations allowed) ----------------
__device__ __align__(16) int   g_hi4 [NM*PARTS];
__device__ __align__(16) int   g_lo4 [NM*PARTS];
__device__ __align__(16) int   g_mnx4[NM*PARTS];
__device__ __align__(16) int   g_mxx4[NM*PARTS];
__device__ __align__(16) int   g_mny4[NM*PARTS];
__device__ __align__(16) int   g_mxy4[NM*PARTS];
__device__ __align__(16) float g_gated[NM];
__device__ int g_done;

// ---------------- pass 1: per-mask stats, 4 blocks per mask ----------------
__global__ __launch_bounds__(256) void stats_kernel(const float* __restrict__ logits) {
    if (blockIdx.x == 0 && threadIdx.x == 0) g_done = 0;   // reset flag for pass 2

    const int b  = blockIdx.x;
    const int n  = b >> 2;
    const int rq = b & 3;
    const float4* __restrict__ p =
        (const float4*)(logits + (size_t)n * HW) + (rq << 12);

    const int xq = threadIdx.x & 63;
    const int y0 = threadIdx.x >> 6;      // 0..3; thread covers rows y0+4k

    int hi = 0, lo = 0;
    unsigned rowm = 0, colm = 0;

    #pragma unroll 8
    for (int k = 0; k < 16; k++) {
        int yy = y0 + (k << 2);
        float4 v = p[(yy << 6) + xq];
        hi += (v.x > 1.f) + (v.y > 1.f) + (v.z > 1.f) + (v.w > 1.f);
        lo += (v.x > -1.f) + (v.y > -1.f) + (v.z > -1.f) + (v.w > -1.f);
        unsigned pm = (unsigned)(v.x > 0.f)        | ((unsigned)(v.y > 0.f) << 1)
                    | ((unsigned)(v.z > 0.f) << 2) | ((unsigned)(v.w > 0.f) << 3);
        colm |= pm;
        rowm |= (pm ? 1u : 0u) << k;
    }

    int mnx = WW, mxx = -1, mny = 64, mxy = -1;
    if (colm) { int bx = xq << 2; mnx = bx + __ffs(colm) - 1; mxx = bx + 31 - __clz(colm); }
    if (rowm) { mny = y0 + ((__ffs(rowm) - 1) << 2); mxy = y0 + ((31 - __clz(rowm)) << 2); }

    #pragma unroll
    for (int o = 16; o > 0; o >>= 1) {
        hi  += __shfl_xor_sync(0xffffffffu, hi, o);
        lo  += __shfl_xor_sync(0xffffffffu, lo, o);
        mnx  = min(mnx, __shfl_xor_sync(0xffffffffu, mnx, o));
        mxx  = max(mxx, __shfl_xor_sync(0xffffffffu, mxx, o));
        mny  = min(mny, __shfl_xor_sync(0xffffffffu, mny, o));
        mxy  = max(mxy, __shfl_xor_sync(0xffffffffu, mxy, o));
    }

    __shared__ int s_hi[8], s_lo[8], s_mnx[8], s_mxx[8], s_mny[8], s_mxy[8];
    int w = threadIdx.x >> 5;
    if ((threadIdx.x & 31) == 0) {
        s_hi[w] = hi; s_lo[w] = lo;
        s_mnx[w] = mnx; s_mxx[w] = mxx; s_mny[w] = mny; s_mxy[w] = mxy;
    }
    __syncthreads();
    if (threadIdx.x == 0) {
        int thi = 0, tlo = 0, tmnx = WW, tmxx = -1, tmny = 64, tmxy = -1;
        #pragma unroll
        for (int i = 0; i < 8; i++) {
            thi += s_hi[i]; tlo += s_lo[i];
            tmnx = min(tmnx, s_mnx[i]); tmxx = max(tmxx, s_mxx[i]);
            tmny = min(tmny, s_mny[i]); tmxy = max(tmxy, s_mxy[i]);
        }
        g_hi4[b] = thi; g_lo4[b] = tlo;
        g_mnx4[b] = tmnx; g_mxx4[b] = tmxx;
        if (tmxy < 0) { g_mny4[b] = HH; g_mxy4[b] = -1; }
        else          { g_mny4[b] = tmny + (rq << 6); g_mxy4[b] = tmxy + (rq << 6); }
    }
}

// ---------------- pass 2: block 0 = NMS; blocks 1.. = full output writers ----------------
__global__ __launch_bounds__(256)
void finish_kernel(const float* __restrict__ logits,
                   const float* __restrict__ iou_preds,
                   float* __restrict__ out,
                   float* __restrict__ out_keep,
                   float* __restrict__ out_boxes) {
    const int t = threadIdx.x;

    if (blockIdx.x != 0) {
        // ---- writer role: one 1/16 mask segment (16 KB) per block ----
        const int b   = blockIdx.x - 1;
        const int n   = b >> 4;
        const int seg = b & 15;

        int4 H = *(const int4*)&g_hi4[n << 2];
        int4 L = *(const int4*)&g_lo4[n << 2];
        int hi = H.x + H.y + H.z + H.w;
        int lo = L.x + L.y + L.z + L.w;
        float stab = (float)hi / fmaxf((float)lo, 1.0f);
        bool valid = (iou_preds[n] > 0.88f) && (stab >= 0.95f);

        float4* __restrict__ o = (float4*)(out + (size_t)n * HW) + (seg << 10);

        if (!valid) {                        // no NMS dependency: zero immediately
            const float4 z = make_float4(0.f, 0.f, 0.f, 0.f);
            #pragma unroll
            for (int k = 0; k < 4; k++)
                o[t + (k << 8)] = z;
            return;
        }

        // valid: wait for NMS result (block 0 is wave-1 resident -> no deadlock)
        if (t == 0) {
            while (*(volatile int*)&g_done == 0) __nanosleep(64);
        }
        __syncthreads();
        __threadfence();
        float g = *(volatile float*)&g_gated[n];

        if (g == 0.f) {                      // valid but NMS-suppressed
            const float4 z = make_float4(0.f, 0.f, 0.f, 0.f);
            #pragma unroll
            for (int k = 0; k < 4; k++)
                o[t + (k << 8)] = z;
        } else {                             // kept: gated sigmoid
            const float4* __restrict__ p =
                (const float4*)(logits + (size_t)n * HW) + (seg << 10);
            #pragma unroll
            for (int k = 0; k < 4; k++) {
                int q = t + (k << 8);
                float4 v = p[q];
                float4 r;
                r.x = g / (1.f + __expf(-v.x));
                r.y = g / (1.f + __expf(-v.y));
                r.z = g / (1.f + __expf(-v.z));
                r.w = g / (1.f + __expf(-v.w));
                o[q] = r;
            }
        }
        return;
    }

    // ---- NMS role: block 0, 256 threads ----
    __shared__ int      s_scan[256];
    __shared__ int      s_cnt;
    __shared__ float    s_cs[MAXC];
    __shared__ float4   s_cb[MAXC];
    __shared__ int      s_co[MAXC];
    __shared__ float    s_sc[PMAX];
    __shared__ int      s_si[PMAX];
    __shared__ float4   s_sb[MAXC];
    __shared__ int      s_so[MAXC];
    __shared__ unsigned s_mat[MAXC][MAXW];
    __shared__ unsigned s_keepw[MAXW];

    const int4* __restrict__ ph  = (const int4*)g_hi4;
    const int4* __restrict__ pl  = (const int4*)g_lo4;
    const int4* __restrict__ px0 = (const int4*)g_mnx4;
    const int4* __restrict__ px1 = (const int4*)g_mxx4;
    const int4* __restrict__ py0 = (const int4*)g_mny4;
    const int4* __restrict__ py1 = (const int4*)g_mxy4;

    bool   vld[4];
    float  scr[4];
    float4 box[4];
    #pragma unroll
    for (int r = 0; r < 4; r++) {
        int m = (t << 2) + r;
        int4 H = ph[m], L = pl[m], X0 = px0[m], X1 = px1[m], Y0 = py0[m], Y1 = py1[m];
        int hi = H.x + H.y + H.z + H.w;
        int lo = L.x + L.y + L.z + L.w;
        int mnx = min(min(X0.x, X0.y), min(X0.z, X0.w));
        int mxx = max(max(X1.x, X1.y), max(X1.z, X1.w));
        int mny = min(min(Y0.x, Y0.y), min(Y0.z, Y0.w));
        int mxy = max(max(Y1.x, Y1.y), max(Y1.z, Y1.w));
        float stab = (float)hi / fmaxf((float)lo, 1.0f);
        float sc = iou_preds[m];
        vld[r] = (sc > 0.88f) && (stab >= 0.95f);
        scr[r] = sc;
        box[r] = (mxy < 0) ? make_float4(0.f, 0.f, 0.f, 0.f)
                           : make_float4((float)mnx, (float)mny, (float)mxx, (float)mxy);
    }

    const float4 z4 = make_float4(0.f, 0.f, 0.f, 0.f);
    ((float4*)g_gated)[t] = z4;
    if (out_keep) ((float4*)out_keep)[t] = z4;
    if (out_boxes) {
        float4* ob = (float4*)out_boxes;
        #pragma unroll
        for (int r = 0; r < 4; r++) ob[(t << 2) + r] = box[r];
    }

    // deterministic order-preserving compaction via scan
    int c = (int)vld[0] + vld[1] + vld[2] + vld[3];
    s_scan[t] = c;
    __syncthreads();
    for (int off = 1; off < 256; off <<= 1) {
        int x = s_scan[t];
        int a = (t >= off) ? s_scan[t - off] : 0;
        __syncthreads();
        s_scan[t] = x + a;
        __syncthreads();
    }
    if (t == 255) s_cnt = s_scan[255];
    int pos = s_scan[t] - c;
    #pragma unroll
    for (int r = 0; r < 4; r++) {
        if (vld[r]) {
            if (pos < MAXC) { s_cs[pos] = scr[r]; s_cb[pos] = box[r]; s_co[pos] = (t << 2) + r; }
            pos++;
        }
    }
    __syncthreads();
    const int cnt = min(s_cnt, MAXC);

    if (cnt > 0) {
        int P = 32;
        while (P < cnt) P <<= 1;               // <= 256
        for (int i = t; i < P; i += 256) { s_sc[i] = (i < cnt) ? s_cs[i] : -CUDART_INF_F; s_si[i] = i; }
        __syncthreads();
        for (int k = 2; k <= P; k <<= 1) {
            for (int j = k >> 1; j > 0; j >>= 1) {
                for (int i = t; i < P; i += 256) {
                    int ixj = i ^ j;
                    if (ixj > i) {
                        float a = s_sc[i], bb = s_sc[ixj];
                        if (((i & k) == 0) ? (a < bb) : (a > bb)) {
                            s_sc[i] = bb; s_sc[ixj] = a;
                            int ti = s_si[i]; s_si[i] = s_si[ixj]; s_si[ixj] = ti;
                        }
                    }
                }
                __syncthreads();
            }
        }
        for (int i = t; i < cnt; i += 256) {
            int src = s_si[i];
            s_sb[i] = s_cb[src];
            s_so[i] = s_co[src];
        }
        __syncthreads();

        // suppression bit-matrix: row i, bit j (j>i) set iff IoU(i,j) > 0.7
        const int W = (cnt + 31) >> 5;
        for (int u = t; u < cnt * W; u += 256) {
            int i = u / W, w = u - i * W;
            float4 bi = s_sb[i];
            float ai = fmaxf(bi.z - bi.x, 0.f) * fmaxf(bi.w - bi.y, 0.f);
            unsigned bits = 0;
            int jb = w << 5;
            for (int b2 = 0; b2 < 32; b2++) {
                int j = jb + b2;
                if (j < cnt && j > i) {
                    float4 bj = s_sb[j];
                    float x0 = fmaxf(bi.x, bj.x), y0 = fmaxf(bi.y, bj.y);
                    float x1 = fminf(bi.z, bj.z), y1 = fminf(bi.w, bj.w);
                    float inter = fmaxf(x1 - x0, 0.f) * fmaxf(y1 - y0, 0.f);
                    float aj = fmaxf(bj.z - bj.x, 0.f) * fmaxf(bj.w - bj.y, 0.f);
                    if (inter / fmaxf(ai + aj - inter, 1e-6f) > 0.7f) bits |= 1u << b2;
                }
            }
            s_mat[i][w] = bits;
        }
        __syncthreads();

        // greedy chain as bitmask scan (single thread)
        if (t == 0) {
            unsigned kw[MAXW];
            #pragma unroll
            for (int w = 0; w < MAXW; w++) {
                if (w < W - 1)       kw[w] = 0xFFFFFFFFu;
                else if (w == W - 1) kw[w] = (cnt & 31) ? ((1u << (cnt & 31)) - 1u) : 0xFFFFFFFFu;
                else                 kw[w] = 0u;
            }
            for (int i = 0; i < cnt; i++) {
                if ((kw[i >> 5] >> (i & 31)) & 1u) {
                    for (int w = 0; w < W; w++) kw[w] &= ~s_mat[i][w];
                }
            }
            for (int w = 0; w < W; w++) s_keepw[w] = kw[w];
        }
        __syncthreads();

        for (int i = t; i < cnt; i += 256) {
            if ((s_keepw[i >> 5] >> (i & 31)) & 1u) {
                int o = s_so[i];
                g_gated[o] = s_sc[i];
                if (out_keep) out_keep[o] = 1.0f;
            }
        }
    }

    // publish results to spinning writer blocks
    __threadfence();
    __syncthreads();
    if (t == 0) *(volatile int*)&g_done = 1;
}

// ---------------- launch ----------------
extern "C" void kernel_launch(void* const* d_in, const int* in_sizes, int n_in,
                              void* d_out, int out_size) {
    const float* logits;
    const float* iou;
    if (in_sizes[0] == NM) { iou = (const float*)d_in[0]; logits = (const float*)d_in[1]; }
    else                   { logits = (const float*)d_in[0]; iou = (const float*)d_in[1]; }

    float* out = (float*)d_out;
    const size_t nhw = (size_t)NM * HW;
    float* out_keep  = nullptr;
    float* out_boxes = nullptr;
    if ((size_t)out_size >= nhw + NM)          out_keep  = out + nhw;
    if ((size_t)out_size >= nhw + NM + 4 * NM) out_boxes = out + nhw + NM;

    stats_kernel<<<NM * PARTS, 256>>>(logits);
    finish_kernel<<<NM * SEGS + 1, 256>>>(logits, iou, out, out_keep, out_boxes);
}